// round 10
// baseline (speedup 1.0000x reference)
#include <cuda_runtime.h>
#include <cuda_fp16.h>
#include <math.h>
#include <stdint.h>

#define R_    2048
#define NODE_ 53
#define H_    512
#define C_    51
#define NOBJ_ 151
#define T_    3
#define RN_   (R_*NODE_)      /* 108544 */
#define K2_   (NODE_*512)     /* 27136  */
#define SPLITS_ 53

// ================= helpers =================
__device__ __forceinline__ void mma_f16(float* d, const uint32_t* a, const uint32_t* b) {
    asm volatile(
        "mma.sync.aligned.m16n8k16.row.col.f32.f16.f16.f32 "
        "{%0,%1,%2,%3}, {%4,%5,%6,%7}, {%8,%9}, {%0,%1,%2,%3};\n"
        : "+f"(d[0]), "+f"(d[1]), "+f"(d[2]), "+f"(d[3])
        : "r"(a[0]), "r"(a[1]), "r"(a[2]), "r"(a[3]), "r"(b[0]), "r"(b[1]));
}
__device__ __forceinline__ void ldsm4(uint32_t* r, uint32_t addr) {
    asm volatile("ldmatrix.sync.aligned.m8n8.x4.shared.b16 {%0,%1,%2,%3}, [%4];"
        : "=r"(r[0]), "=r"(r[1]), "=r"(r[2]), "=r"(r[3]) : "r"(addr));
}
__device__ __forceinline__ uint32_t smem_u32(const void* p) {
    uint32_t a;
    asm("{ .reg .u64 t; cvta.to.shared.u64 t, %1; cvt.u32.u64 %0, t; }" : "=r"(a) : "l"(p));
    return a;
}
__device__ __forceinline__ void cp_async16(uint32_t s, const void* g) {
    asm volatile("cp.async.cg.shared.global [%0], [%1], 16;" :: "r"(s), "l"(g));
}
#define CP_COMMIT() asm volatile("cp.async.commit_group;" ::: "memory")
#define CP_WAIT(n)  asm volatile("cp.async.wait_group %0;" :: "n"(n) : "memory")

// ================= scratch =================
__device__ __half g_hid0 [RN_*H_];
__device__ __half g_hid1 [RN_*H_];
__device__ __half g_inp  [RN_*H_];
__device__ __half g_sa   [2*R_*H_];
__device__ __half g_rf   [RN_*H_];
__device__ __half g_out  [RN_*H_];
__device__ __half g_weff [3*H_*H_];
__device__ __half g_ucat [3*H_*H_];
__device__ __half g_wor  [2*H_*H_];
__device__ __half g_wc   [128*K2_];
__device__ float  g_z    [RN_*H_];
__device__ float  g_Y    [2*R_*3*H_];
__device__ float  g_bias [3*H_];
__device__ float  g_row  [R_*C_];
__device__ float  g_coef [RN_];
__device__ int    g_yrow [RN_];
__device__ float  g_part [SPLITS_*R_*C_];

// ================= combined prep (includes input fp32->fp16) =================
#define PREP_IN_  (RN_*H_/2)          /* half2 elements of input */
#define PREP_W_   (3*H_*H_)
#define PREP_WO_  (2*H_*H_)
#define PREP_ROW_ (R_*C_)
#define PREP_CY_  (RN_)
#define PREP_WC_  (128*K2_)
#define PREP_TOTAL_ (PREP_IN_ + PREP_W_ + PREP_WO_ + PREP_ROW_ + PREP_CY_ + PREP_WC_)

__global__ void k_prep_all(
    const int* __restrict__ sop, const float* __restrict__ matrix,
    const float* w3w, const float* w3u, const float* b3w, const float* b3u,
    const float* w4w, const float* w4u, const float* b4w, const float* b4u,
    const float* w5w, const float* w5u, const float* b5w, const float* b5u,
    const float* __restrict__ wo, const float* __restrict__ wc,
    const float* __restrict__ input)
{
    int i = blockIdx.x*blockDim.x + threadIdx.x;
    if (i < PREP_IN_) {
        float2 v = ((const float2*)input)[i];
        ((__half2*)g_inp)[i] = __floats2half2_rn(v.x, v.y);
        return;
    }
    i -= PREP_IN_;
    if (i < PREP_W_) {
        int g = i / (H_*H_);
        int rem = i - g*(H_*H_);
        int h = rem / H_, k = rem - h*H_;
        const float* ww = (g==0) ? w3w : (g==1) ? w4w : w5w;
        const float* wu = (g==0) ? w3u : (g==1) ? w4u : w5u;
        g_weff[i] = __float2half_rn(ww[h*(2*H_) + k] + ww[h*(2*H_) + H_ + k]);
        g_ucat[i] = __float2half_rn(wu[rem]);
        if (i < 3*H_) {
            int gg = i / H_, h2 = i - gg*H_;
            const float* bw = (gg==0) ? b3w : (gg==1) ? b4w : b5w;
            const float* bu = (gg==0) ? b3u : (gg==1) ? b4u : b5u;
            g_bias[i] = bw[h2] + bu[h2];
        }
    } else if (i < PREP_W_ + PREP_WO_) {
        int j = i - PREP_W_;
        int row = j >> 10, col = j & 1023;
        int dst = (col < H_) ? row*H_ + col : (row + H_)*H_ + (col - H_);
        g_wor[dst] = __float2half_rn(wo[j]);
    } else if (i < PREP_W_ + PREP_WO_ + PREP_ROW_) {
        int j = i - PREP_W_ - PREP_WO_;
        int r = j / C_, c = j - r*C_;
        g_row[j] = matrix[((size_t)sop[2*r]*NOBJ_ + sop[2*r+1])*C_ + c];
    } else if (i < PREP_W_ + PREP_WO_ + PREP_ROW_ + PREP_CY_) {
        int j = i - PREP_W_ - PREP_WO_ - PREP_ROW_;
        int r = j / NODE_, e = j - r*NODE_;
        if (e < 2) { g_coef[j] = 1.f; g_yrow[j] = r; }
        else {
            g_coef[j] = matrix[((size_t)sop[2*r]*NOBJ_ + sop[2*r+1])*C_ + (e-2)];
            g_yrow[j] = R_ + r;
        }
    } else if (i < PREP_W_ + PREP_WO_ + PREP_ROW_ + PREP_CY_ + PREP_WC_) {
        int j = i - PREP_W_ - PREP_WO_ - PREP_ROW_ - PREP_CY_;
        int row = j / K2_, col = j - row*K2_;
        g_wc[j] = (row < C_) ? __float2half_rn(wc[(size_t)row*K2_ + col]) : __float2half_rn(0.f);
    }
}

// ================= av =================
__global__ void __launch_bounds__(256) k_av(const __half* __restrict__ hid) {
    __shared__ float srow[C_];
    int r = blockIdx.x;
    if (threadIdx.x < C_) srow[threadIdx.x] = g_row[r*C_ + threadIdx.x];
    __syncthreads();
    int h2i = threadIdx.x;
    const __half2* hb = (const __half2*)(hid + (size_t)r*NODE_*H_);
    float2 a0 = __half22float2(hb[h2i]);
    float2 a1 = __half22float2(hb[256 + h2i]);
    float sx = a0.x + a1.x, sy = a0.y + a1.y;
    float ax = 0.f, ay = 0.f;
    #pragma unroll 3
    for (int c = 0; c < C_; ++c) {
        float rc = srow[c];
        float2 v = __half22float2(hb[(2+c)*256 + h2i]);
        ax = fmaf(rc, v.x, ax);
        ay = fmaf(rc, v.y, ay);
    }
    __half2* sa = (__half2*)g_sa;
    sa[(size_t)r*256 + h2i]        = __floats2half2_rn(ax, ay);
    sa[(size_t)(R_+r)*256 + h2i]   = __floats2half2_rn(sx, sy);
}

// ===== fp16 mma GEMM: CTA 256x128, 16 warps (4x4), warp tile 64x32 ==========
#define ACT_NONE 0
#define ACT_GATE 1
#define ACT_GRU  2
#define ACT_RELU 3

#define ROWB_     144
#define STG_A     (256*ROWB_)              /* 36864: A region (256 rows) */
#define STG_BYTES (STG_A + 128*ROWB_)      /* 55296 */
#define SMEM_BYTES (3*STG_BYTES)           /* 165888 */

template<int ACT, int NTERMS, bool SPLITK>
__global__ void __launch_bounds__(512, 1) k_hmma(
    const __half* __restrict__ A1, int lda1, const __half* __restrict__ W1, int ldw1,
    const __half* __restrict__ A2, const __half* __restrict__ W2,
    const float* __restrict__ bias,
    const __half* __restrict__ hidin,
    const float* __restrict__ zbuf,
    int ycol0,
    float* __restrict__ Yco, int ldy, int nmax,
    __half* __restrict__ Ho)
{
    extern __shared__ __align__(16) char smc[];
    const uint32_t smem_base = smem_u32(smc);
    const int tid  = threadIdx.x;
    const int lane = tid & 31;
    const int wid  = tid >> 5;            // 0..15
    const int wm   = wid >> 2;            // 0..3  (64-row strip)
    const int wn   = wid & 3;             // 0..3  (32-col strip)
    const int blockRow = blockIdx.y * 256;
    const int blockCol = blockIdx.x * 128;
    const int kbeg = SPLITK ? blockIdx.z * 512 : 0;

    float acc[4][4][4];
    #pragma unroll
    for (int i = 0; i < 4; ++i)
        #pragma unroll
        for (int j = 0; j < 4; ++j)
            #pragma unroll
            for (int v = 0; v < 4; ++v) acc[i][j][v] = 0.f;

    const int mrow = tid >> 3;     // 0..63
    const int qk   = tid & 7;

    uint32_t aoff[4], boff[2];
    {
        const int rw = lane & 7;
        const int g1 = (lane >> 3) & 1;
        const int g2 = lane >> 4;
        #pragma unroll
        for (int i = 0; i < 4; ++i)
            aoff[i] = (uint32_t)(wm*64 + i*16 + rw + g1*8)*ROWB_ + g2*16;
        #pragma unroll
        for (int jj = 0; jj < 2; ++jj)
            boff[jj] = STG_A + (uint32_t)(wn*32 + jj*16 + rw + g2*8)*ROWB_ + g1*16;
    }

    auto load_chunk = [&](int c, int stage) {
        const int term = c >> 3;
        const int kk0  = kbeg + (c & 7) * 64;
        const __half* A = term ? A2 : A1;  const int lda = term ? 512 : lda1;
        const __half* W = term ? W2 : W1;  const int ldw = term ? 512 : ldw1;
        const __half* Ag = A + (size_t)(blockRow + mrow)*lda + kk0 + qk*8;
        const __half* Wg = W + (size_t)(blockCol + mrow)*ldw + kk0 + qk*8;
        uint32_t sa = smem_base + stage*STG_BYTES + mrow*ROWB_ + qk*16;
        uint32_t sb = sa + STG_A;
        #pragma unroll
        for (int p = 0; p < 4; ++p)          // A: 256 rows
            cp_async16(sa + p*64*ROWB_, Ag + (size_t)p*64*lda);
        #pragma unroll
        for (int p = 0; p < 2; ++p)          // B: 128 rows
            cp_async16(sb + p*64*ROWB_, Wg + (size_t)p*64*ldw);
    };

    auto compute = [&](int stage) {
        const uint32_t sbase = smem_base + stage*STG_BYTES;
        #pragma unroll
        for (int s = 0; s < 4; ++s) {
            uint32_t af[4][4], bf[2][4];
            #pragma unroll
            for (int i = 0; i < 4; ++i)   ldsm4(af[i],  sbase + aoff[i]  + s*32);
            #pragma unroll
            for (int jj = 0; jj < 2; ++jj) ldsm4(bf[jj], sbase + boff[jj] + s*32);
            #pragma unroll
            for (int i = 0; i < 4; ++i)
                #pragma unroll
                for (int jj = 0; jj < 2; ++jj) {
                    mma_f16(acc[i][2*jj],   af[i], &bf[jj][0]);
                    mma_f16(acc[i][2*jj+1], af[i], &bf[jj][2]);
                }
        }
    };

    const int NCH = 8*NTERMS;
    load_chunk(0, 0); CP_COMMIT();
    load_chunk(1, 1); CP_COMMIT();

    int stage_n = 2;
    for (int c = 0; c < NCH; ++c) {
        CP_WAIT(1);
        __syncthreads();
        if (c + 2 < NCH) load_chunk(c + 2, stage_n);
        CP_COMMIT();
        int stage_c = stage_n + 1; if (stage_c >= 3) stage_c -= 3;
        compute(stage_c);
        stage_n = stage_c;
    }
    CP_WAIT(0);

    // ---- epilogue
    const size_t zoff = SPLITK ? (size_t)blockIdx.z * (R_*C_) : 0;
    #pragma unroll
    for (int i = 0; i < 4; ++i) {
        const int r0 = blockRow + wm*64 + i*16 + (lane >> 2);
        float cf0 = 0.f, cf1 = 0.f;
        const float *y0p = nullptr, *y1p = nullptr;
        if (ACT == ACT_GATE || ACT == ACT_GRU) {
            cf0 = g_coef[r0];     y0p = g_Y + (size_t)g_yrow[r0]*1536   + ycol0;
            cf1 = g_coef[r0+8];   y1p = g_Y + (size_t)g_yrow[r0+8]*1536 + ycol0;
        }
        #pragma unroll
        for (int j = 0; j < 4; ++j) {
            const int gc = blockCol + wn*32 + j*8 + (lane & 3)*2;
            float v0 = acc[i][j][0];
            float v1 = acc[i][j][1];
            float v2 = acc[i][j][2];
            float v3 = acc[i][j][3];
            if (ACT != ACT_NONE) {
                float2 bs = *(const float2*)&bias[gc];
                v0 += bs.x; v1 += bs.y; v2 += bs.x; v3 += bs.y;
            }
            if (ACT == ACT_GATE || ACT == ACT_GRU) {
                float2 y0 = *(const float2*)&y0p[gc];
                float2 y1 = *(const float2*)&y1p[gc];
                v0 = fmaf(cf0, y0.x, v0); v1 = fmaf(cf0, y0.y, v1);
                v2 = fmaf(cf1, y1.x, v2); v3 = fmaf(cf1, y1.y, v3);
            }
            if (ACT == ACT_NONE) {
                if (SPLITK) {
                    if (gc < nmax) {
                        Yco[zoff + (size_t)r0*ldy + gc]     = v0;
                        Yco[zoff + (size_t)(r0+8)*ldy + gc] = v2;
                    }
                    if (gc + 1 < nmax) {
                        Yco[zoff + (size_t)r0*ldy + gc + 1]     = v1;
                        Yco[zoff + (size_t)(r0+8)*ldy + gc + 1] = v3;
                    }
                } else {
                    *(float2*)&Yco[(size_t)r0*ldy + gc]     = make_float2(v0, v1);
                    *(float2*)&Yco[(size_t)(r0+8)*ldy + gc] = make_float2(v2, v3);
                }
            } else if (ACT == ACT_GATE) {
                float s0 = 1.f/(1.f+__expf(-v0)), s1 = 1.f/(1.f+__expf(-v1));
                float s2 = 1.f/(1.f+__expf(-v2)), s3 = 1.f/(1.f+__expf(-v3));
                if (gc < 512) {
                    *(float2*)&g_z[(size_t)r0*512 + gc]     = make_float2(s0, s1);
                    *(float2*)&g_z[(size_t)(r0+8)*512 + gc] = make_float2(s2, s3);
                } else {
                    const int hc = gc - 512;
                    float2 f0 = __half22float2(*(const __half2*)&hidin[(size_t)r0*512 + hc]);
                    float2 f1 = __half22float2(*(const __half2*)&hidin[(size_t)(r0+8)*512 + hc]);
                    *(__half2*)&g_rf[(size_t)r0*512 + hc]     = __floats2half2_rn(s0*f0.x, s1*f0.y);
                    *(__half2*)&g_rf[(size_t)(r0+8)*512 + hc] = __floats2half2_rn(s2*f1.x, s3*f1.y);
                }
            } else if (ACT == ACT_RELU) {
                *(__half2*)&Ho[(size_t)r0*512 + gc]     = __floats2half2_rn(fmaxf(v0,0.f), fmaxf(v1,0.f));
                *(__half2*)&Ho[(size_t)(r0+8)*512 + gc] = __floats2half2_rn(fmaxf(v2,0.f), fmaxf(v3,0.f));
            } else {  // GRU
                float2 z0 = *(const float2*)&zbuf[(size_t)r0*512 + gc];
                float2 z1 = *(const float2*)&zbuf[(size_t)(r0+8)*512 + gc];
                float2 f0 = __half22float2(*(const __half2*)&hidin[(size_t)r0*512 + gc]);
                float2 f1 = __half22float2(*(const __half2*)&hidin[(size_t)(r0+8)*512 + gc]);
                float o0 = (1.f-z0.x)*f0.x + z0.x*tanhf(v0);
                float o1 = (1.f-z0.y)*f0.y + z0.y*tanhf(v1);
                float o2 = (1.f-z1.x)*f1.x + z1.x*tanhf(v2);
                float o3 = (1.f-z1.y)*f1.y + z1.y*tanhf(v3);
                *(__half2*)&Ho[(size_t)r0*512 + gc]     = __floats2half2_rn(o0, o1);
                *(__half2*)&Ho[(size_t)(r0+8)*512 + gc] = __floats2half2_rn(o2, o3);
            }
        }
    }
}

__global__ void k_reduce(const float* __restrict__ bc, float* __restrict__ out) {
    int i = blockIdx.x*blockDim.x + threadIdx.x;
    if (i >= R_*C_) return;
    float s = bc[i % C_];
    for (int z = 0; z < SPLITS_; ++z) s += g_part[(size_t)z*(R_*C_) + i];
    out[i] = s;
}

// ================= launch =================
extern "C" void kernel_launch(void* const* d_in, const int* in_sizes, int n_in,
                              void* d_out, int out_size) {
    const int*   sop    = (const int*)  d_in[1];
    const float* input  = (const float*)d_in[2];
    const float* matrix = (const float*)d_in[4];
    const float* w3w = (const float*)d_in[5];  const float* b3w = (const float*)d_in[6];
    const float* w3u = (const float*)d_in[7];  const float* b3u = (const float*)d_in[8];
    const float* w4w = (const float*)d_in[9];  const float* b4w = (const float*)d_in[10];
    const float* w4u = (const float*)d_in[11]; const float* b4u = (const float*)d_in[12];
    const float* w5w = (const float*)d_in[13]; const float* b5w = (const float*)d_in[14];
    const float* w5u = (const float*)d_in[15]; const float* b5u = (const float*)d_in[16];
    const float* wo  = (const float*)d_in[17]; const float* bo  = (const float*)d_in[18];
    const float* wc  = (const float*)d_in[19]; const float* bc  = (const float*)d_in[20];
    float* out = (float*)d_out;

    __half *p_h0, *p_h1, *p_inp, *p_sa, *p_rf, *p_out, *p_weff, *p_ucat, *p_wor, *p_wc;
    float  *p_Y, *p_z, *p_bias, *p_part;
    cudaGetSymbolAddress((void**)&p_h0,   g_hid0);
    cudaGetSymbolAddress((void**)&p_h1,   g_hid1);
    cudaGetSymbolAddress((void**)&p_inp,  g_inp);
    cudaGetSymbolAddress((void**)&p_sa,   g_sa);
    cudaGetSymbolAddress((void**)&p_rf,   g_rf);
    cudaGetSymbolAddress((void**)&p_out,  g_out);
    cudaGetSymbolAddress((void**)&p_weff, g_weff);
    cudaGetSymbolAddress((void**)&p_ucat, g_ucat);
    cudaGetSymbolAddress((void**)&p_wor,  g_wor);
    cudaGetSymbolAddress((void**)&p_wc,   g_wc);
    cudaGetSymbolAddress((void**)&p_Y,    g_Y);
    cudaGetSymbolAddress((void**)&p_z,    g_z);
    cudaGetSymbolAddress((void**)&p_bias, g_bias);
    cudaGetSymbolAddress((void**)&p_part, g_part);

    cudaFuncSetAttribute(k_hmma<ACT_NONE,1,false>, cudaFuncAttributeMaxDynamicSharedMemorySize, SMEM_BYTES);
    cudaFuncSetAttribute(k_hmma<ACT_NONE,1,true>,  cudaFuncAttributeMaxDynamicSharedMemorySize, SMEM_BYTES);
    cudaFuncSetAttribute(k_hmma<ACT_GATE,1,false>, cudaFuncAttributeMaxDynamicSharedMemorySize, SMEM_BYTES);
    cudaFuncSetAttribute(k_hmma<ACT_GRU,1,false>,  cudaFuncAttributeMaxDynamicSharedMemorySize, SMEM_BYTES);
    cudaFuncSetAttribute(k_hmma<ACT_RELU,2,false>, cudaFuncAttributeMaxDynamicSharedMemorySize, SMEM_BYTES);

    k_prep_all<<<(PREP_TOTAL_ + 255)/256, 256>>>(sop, matrix,
        w3w, w3u, b3w, b3u, w4w, w4u, b4w, b4u, w5w, w5u, b5w, b5u, wo, wc, input);

    dim3 gY   (1536/128, 4096/256);   // 12 x 16
    dim3 gGate(1024/128, RN_/256);    // 8 x 424
    dim3 gHv  (512/128,  RN_/256);    // 4 x 424
    dim3 gFin (1, R_/256, SPLITS_);   // 1 x 8 x 53

    __half* hin = p_inp;
    __half* houts[3] = {p_h0, p_h1, p_h0};
    for (int t = 0; t < T_; ++t) {
        __half* hout = houts[t];
        k_av<<<R_, 256>>>(hin);
        k_hmma<ACT_NONE,1,false><<<gY, 512, SMEM_BYTES>>>(
            p_sa, 512, p_weff, 512, nullptr, nullptr,
            nullptr, nullptr, nullptr, 0, p_Y, 1536, 1536, nullptr);
        k_hmma<ACT_GATE,1,false><<<gGate, 512, SMEM_BYTES>>>(
            hin, 512, p_ucat, 512, nullptr, nullptr,
            p_bias, hin, nullptr, 0, nullptr, 0, 0, nullptr);
        k_hmma<ACT_GRU,1,false><<<gHv, 512, SMEM_BYTES>>>(
            p_rf, 512, p_ucat + 2*H_*H_, 512, nullptr, nullptr,
            p_bias + 2*H_, hin, p_z, 1024, nullptr, 0, 0, hout);
        hin = hout;
    }

    k_hmma<ACT_RELU,2,false><<<gHv, 512, SMEM_BYTES>>>(
        hin, 512, p_wor, 512, p_inp, p_wor + H_*H_,
        bo, nullptr, nullptr, 0, nullptr, 0, 0, p_out);

    k_hmma<ACT_NONE,1,true><<<gFin, 512, SMEM_BYTES>>>(
        p_out, K2_, p_wc, K2_, nullptr, nullptr,
        nullptr, nullptr, nullptr, 0, p_part, C_, C_, nullptr);
    k_reduce<<<(R_*C_ + 255)/256, 256>>>(bc, out);
}

// round 11
// speedup vs baseline: 1.0912x; 1.0912x over previous
#include <cuda_runtime.h>
#include <cuda_fp16.h>
#include <math.h>
#include <stdint.h>

#define R_    2048
#define NODE_ 53
#define H_    512
#define C_    51
#define NOBJ_ 151
#define T_    3
#define RN_   (R_*NODE_)      /* 108544 */
#define K2_   (NODE_*512)     /* 27136  */
#define SPLITS_ 53

// ================= helpers =================
__device__ __forceinline__ void mma_f16(float* d, const uint32_t* a, const uint32_t* b) {
    asm volatile(
        "mma.sync.aligned.m16n8k16.row.col.f32.f16.f16.f32 "
        "{%0,%1,%2,%3}, {%4,%5,%6,%7}, {%8,%9}, {%0,%1,%2,%3};\n"
        : "+f"(d[0]), "+f"(d[1]), "+f"(d[2]), "+f"(d[3])
        : "r"(a[0]), "r"(a[1]), "r"(a[2]), "r"(a[3]), "r"(b[0]), "r"(b[1]));
}
__device__ __forceinline__ void ldsm4(uint32_t* r, uint32_t addr) {
    asm volatile("ldmatrix.sync.aligned.m8n8.x4.shared.b16 {%0,%1,%2,%3}, [%4];"
        : "=r"(r[0]), "=r"(r[1]), "=r"(r[2]), "=r"(r[3]) : "r"(addr));
}
__device__ __forceinline__ uint32_t smem_u32(const void* p) {
    uint32_t a;
    asm("{ .reg .u64 t; cvta.to.shared.u64 t, %1; cvt.u32.u64 %0, t; }" : "=r"(a) : "l"(p));
    return a;
}
__device__ __forceinline__ void cp_async16(uint32_t s, const void* g) {
    asm volatile("cp.async.cg.shared.global [%0], [%1], 16;" :: "r"(s), "l"(g));
}
#define CP_COMMIT() asm volatile("cp.async.commit_group;" ::: "memory")
#define CP_WAIT(n)  asm volatile("cp.async.wait_group %0;" :: "n"(n) : "memory")

// ================= scratch =================
__device__ __half g_hid0 [RN_*H_];
__device__ __half g_hid1 [RN_*H_];
__device__ __half g_inp  [RN_*H_];
__device__ __half g_sa   [2*R_*H_];
__device__ __half g_rf   [RN_*H_];
__device__ __half g_out  [RN_*H_];
__device__ __half g_weff [3*H_*H_];
__device__ __half g_ucat [3*H_*H_];
__device__ __half g_wor  [2*H_*H_];
__device__ __half g_wc   [128*K2_];
__device__ float  g_z    [RN_*H_];
__device__ float  g_Y    [2*R_*3*H_];
__device__ float  g_bias [3*H_];
__device__ float  g_row  [R_*C_];
__device__ float  g_coef [RN_];
__device__ int    g_yrow [RN_];
__device__ float  g_part [SPLITS_*R_*C_];

// ========== combined prep (weights + metadata + input fp32->fp16) ==========
#define PREP_IN_  (RN_*H_/2)
#define PREP_W_   (3*H_*H_)
#define PREP_WO_  (2*H_*H_)
#define PREP_ROW_ (R_*C_)
#define PREP_CY_  (RN_)
#define PREP_WC_  (128*K2_)
#define PREP_TOTAL_ (PREP_IN_ + PREP_W_ + PREP_WO_ + PREP_ROW_ + PREP_CY_ + PREP_WC_)

__global__ void k_prep_all(
    const int* __restrict__ sop, const float* __restrict__ matrix,
    const float* w3w, const float* w3u, const float* b3w, const float* b3u,
    const float* w4w, const float* w4u, const float* b4w, const float* b4u,
    const float* w5w, const float* w5u, const float* b5w, const float* b5u,
    const float* __restrict__ wo, const float* __restrict__ wc,
    const float* __restrict__ input)
{
    int i = blockIdx.x*blockDim.x + threadIdx.x;
    if (i < PREP_IN_) {
        float2 v = ((const float2*)input)[i];
        ((__half2*)g_inp)[i] = __floats2half2_rn(v.x, v.y);
        return;
    }
    i -= PREP_IN_;
    if (i < PREP_W_) {
        int g = i / (H_*H_);
        int rem = i - g*(H_*H_);
        int h = rem / H_, k = rem - h*H_;
        const float* ww = (g==0) ? w3w : (g==1) ? w4w : w5w;
        const float* wu = (g==0) ? w3u : (g==1) ? w4u : w5u;
        g_weff[i] = __float2half_rn(ww[h*(2*H_) + k] + ww[h*(2*H_) + H_ + k]);
        g_ucat[i] = __float2half_rn(wu[rem]);
        if (i < 3*H_) {
            int gg = i / H_, h2 = i - gg*H_;
            const float* bw = (gg==0) ? b3w : (gg==1) ? b4w : b5w;
            const float* bu = (gg==0) ? b3u : (gg==1) ? b4u : b5u;
            g_bias[i] = bw[h2] + bu[h2];
        }
    } else if (i < PREP_W_ + PREP_WO_) {
        int j = i - PREP_W_;
        int row = j >> 10, col = j & 1023;
        int dst = (col < H_) ? row*H_ + col : (row + H_)*H_ + (col - H_);
        g_wor[dst] = __float2half_rn(wo[j]);
    } else if (i < PREP_W_ + PREP_WO_ + PREP_ROW_) {
        int j = i - PREP_W_ - PREP_WO_;
        int r = j / C_, c = j - r*C_;
        g_row[j] = matrix[((size_t)sop[2*r]*NOBJ_ + sop[2*r+1])*C_ + c];
    } else if (i < PREP_W_ + PREP_WO_ + PREP_ROW_ + PREP_CY_) {
        int j = i - PREP_W_ - PREP_WO_ - PREP_ROW_;
        int r = j / NODE_, e = j - r*NODE_;
        if (e < 2) { g_coef[j] = 1.f; g_yrow[j] = r; }
        else {
            g_coef[j] = matrix[((size_t)sop[2*r]*NOBJ_ + sop[2*r+1])*C_ + (e-2)];
            g_yrow[j] = R_ + r;
        }
    } else if (i < PREP_W_ + PREP_WO_ + PREP_ROW_ + PREP_CY_ + PREP_WC_) {
        int j = i - PREP_W_ - PREP_WO_ - PREP_ROW_ - PREP_CY_;
        int row = j / K2_, col = j - row*K2_;
        g_wc[j] = (row < C_) ? __float2half_rn(wc[(size_t)row*K2_ + col]) : __float2half_rn(0.f);
    }
}

// ================= av =================
__global__ void __launch_bounds__(256) k_av(const __half* __restrict__ hid) {
    __shared__ float srow[C_];
    int r = blockIdx.x;
    if (threadIdx.x < C_) srow[threadIdx.x] = g_row[r*C_ + threadIdx.x];
    __syncthreads();
    int h2i = threadIdx.x;
    const __half2* hb = (const __half2*)(hid + (size_t)r*NODE_*H_);
    float2 a0 = __half22float2(hb[h2i]);
    float2 a1 = __half22float2(hb[256 + h2i]);
    float sx = a0.x + a1.x, sy = a0.y + a1.y;
    float ax = 0.f, ay = 0.f;
    #pragma unroll 3
    for (int c = 0; c < C_; ++c) {
        float rc = srow[c];
        float2 v = __half22float2(hb[(2+c)*256 + h2i]);
        ax = fmaf(rc, v.x, ax);
        ay = fmaf(rc, v.y, ay);
    }
    __half2* sa = (__half2*)g_sa;
    sa[(size_t)r*256 + h2i]        = __floats2half2_rn(ax, ay);
    sa[(size_t)(R_+r)*256 + h2i]   = __floats2half2_rn(sx, sy);
}

// ===== fp16 mma GEMM: CTA 128x128, 8 warps (2x4), warp tile 64x32 ===========
#define ACT_NONE 0
#define ACT_GATE 1
#define ACT_GRU  2
#define ACT_RELU 3

#define ROWB_     144
#define STG_AB    (128*ROWB_)              /* 18432 */
#define STG_BYTES (2*STG_AB)               /* 36864 */
#define SMEM_BYTES (3*STG_BYTES)           /* 110592 */

template<int ACT, int NTERMS, bool SPLITK>
__global__ void __launch_bounds__(256, 2) k_hmma(
    const __half* __restrict__ A1, int lda1, const __half* __restrict__ W1, int ldw1,
    const __half* __restrict__ A2, const __half* __restrict__ W2,
    const float* __restrict__ bias,
    const __half* __restrict__ hidin,
    const float* __restrict__ zbuf,
    int ycol0,
    float* __restrict__ Yco, int ldy, int nmax,
    __half* __restrict__ Ho)
{
    extern __shared__ __align__(16) char smc[];
    const uint32_t smem_base = smem_u32(smc);
    const int tid  = threadIdx.x;
    const int lane = tid & 31;
    const int wid  = tid >> 5;            // 0..7
    const int wm   = wid >> 2;            // 0..1
    const int wn   = wid & 3;             // 0..3
    const int blockRow = blockIdx.y * 128;
    const int blockCol = blockIdx.x * 128;
    const int kbeg = SPLITK ? blockIdx.z * 512 : 0;

    float acc[4][4][4];
    #pragma unroll
    for (int i = 0; i < 4; ++i)
        #pragma unroll
        for (int j = 0; j < 4; ++j)
            #pragma unroll
            for (int v = 0; v < 4; ++v) acc[i][j][v] = 0.f;

    const int mrow = tid >> 3;
    const int qk   = tid & 7;

    uint32_t aoff[4], boff[2];
    {
        const int rw = lane & 7;
        const int g1 = (lane >> 3) & 1;
        const int g2 = lane >> 4;
        #pragma unroll
        for (int i = 0; i < 4; ++i)
            aoff[i] = (uint32_t)(wm*64 + i*16 + rw + g1*8)*ROWB_ + g2*16;
        #pragma unroll
        for (int jj = 0; jj < 2; ++jj)
            boff[jj] = STG_AB + (uint32_t)(wn*32 + jj*16 + rw + g2*8)*ROWB_ + g1*16;
    }

    auto load_chunk = [&](int c, int stage) {
        const int term = c >> 3;
        const int kk0  = kbeg + (c & 7) * 64;
        const __half* A = term ? A2 : A1;  const int lda = term ? 512 : lda1;
        const __half* W = term ? W2 : W1;  const int ldw = term ? 512 : ldw1;
        const __half* Ag = A + (size_t)(blockRow + mrow)*lda + kk0 + qk*8;
        const __half* Wg = W + (size_t)(blockCol + mrow)*ldw + kk0 + qk*8;
        uint32_t sa = smem_base + stage*STG_BYTES + mrow*ROWB_ + qk*16;
        uint32_t sb = sa + STG_AB;
        #pragma unroll
        for (int p = 0; p < 4; ++p) {
            cp_async16(sa + p*32*ROWB_, Ag + (size_t)p*32*lda);
            cp_async16(sb + p*32*ROWB_, Wg + (size_t)p*32*ldw);
        }
    };

    auto compute = [&](int stage) {
        const uint32_t sbase = smem_base + stage*STG_BYTES;
        #pragma unroll
        for (int s = 0; s < 4; ++s) {
            uint32_t af[4][4], bf[2][4];
            #pragma unroll
            for (int i = 0; i < 4; ++i)   ldsm4(af[i],  sbase + aoff[i]  + s*32);
            #pragma unroll
            for (int jj = 0; jj < 2; ++jj) ldsm4(bf[jj], sbase + boff[jj] + s*32);
            #pragma unroll
            for (int i = 0; i < 4; ++i)
                #pragma unroll
                for (int jj = 0; jj < 2; ++jj) {
                    mma_f16(acc[i][2*jj],   af[i], &bf[jj][0]);
                    mma_f16(acc[i][2*jj+1], af[i], &bf[jj][2]);
                }
        }
    };

    const int NCH = 8*NTERMS;
    load_chunk(0, 0); CP_COMMIT();
    load_chunk(1, 1); CP_COMMIT();

    int stage_n = 2;
    for (int c = 0; c < NCH; ++c) {
        CP_WAIT(1);
        __syncthreads();
        if (c + 2 < NCH) load_chunk(c + 2, stage_n);
        CP_COMMIT();
        int stage_c = stage_n + 1; if (stage_c >= 3) stage_c -= 3;
        compute(stage_c);
        stage_n = stage_c;
    }
    CP_WAIT(0);

    // ---- epilogue
    const size_t zoff = SPLITK ? (size_t)blockIdx.z * (R_*C_) : 0;
    #pragma unroll
    for (int i = 0; i < 4; ++i) {
        const int r0 = blockRow + wm*64 + i*16 + (lane >> 2);
        float cf0 = 0.f, cf1 = 0.f;
        const float *y0p = nullptr, *y1p = nullptr;
        if (ACT == ACT_GATE || ACT == ACT_GRU) {
            cf0 = g_coef[r0];     y0p = g_Y + (size_t)g_yrow[r0]*1536   + ycol0;
            cf1 = g_coef[r0+8];   y1p = g_Y + (size_t)g_yrow[r0+8]*1536 + ycol0;
        }
        #pragma unroll
        for (int j = 0; j < 4; ++j) {
            const int gc = blockCol + wn*32 + j*8 + (lane & 3)*2;
            float v0 = acc[i][j][0];
            float v1 = acc[i][j][1];
            float v2 = acc[i][j][2];
            float v3 = acc[i][j][3];
            if (ACT != ACT_NONE) {
                float2 bs = *(const float2*)&bias[gc];
                v0 += bs.x; v1 += bs.y; v2 += bs.x; v3 += bs.y;
            }
            if (ACT == ACT_GATE || ACT == ACT_GRU) {
                float2 y0 = *(const float2*)&y0p[gc];
                float2 y1 = *(const float2*)&y1p[gc];
                v0 = fmaf(cf0, y0.x, v0); v1 = fmaf(cf0, y0.y, v1);
                v2 = fmaf(cf1, y1.x, v2); v3 = fmaf(cf1, y1.y, v3);
            }
            if (ACT == ACT_NONE) {
                if (SPLITK) {
                    if (gc < nmax) {
                        Yco[zoff + (size_t)r0*ldy + gc]     = v0;
                        Yco[zoff + (size_t)(r0+8)*ldy + gc] = v2;
                    }
                    if (gc + 1 < nmax) {
                        Yco[zoff + (size_t)r0*ldy + gc + 1]     = v1;
                        Yco[zoff + (size_t)(r0+8)*ldy + gc + 1] = v3;
                    }
                } else {
                    *(float2*)&Yco[(size_t)r0*ldy + gc]     = make_float2(v0, v1);
                    *(float2*)&Yco[(size_t)(r0+8)*ldy + gc] = make_float2(v2, v3);
                }
            } else if (ACT == ACT_GATE) {
                float s0 = 1.f/(1.f+__expf(-v0)), s1 = 1.f/(1.f+__expf(-v1));
                float s2 = 1.f/(1.f+__expf(-v2)), s3 = 1.f/(1.f+__expf(-v3));
                if (gc < 512) {
                    *(float2*)&g_z[(size_t)r0*512 + gc]     = make_float2(s0, s1);
                    *(float2*)&g_z[(size_t)(r0+8)*512 + gc] = make_float2(s2, s3);
                } else {
                    const int hc = gc - 512;
                    float2 f0 = __half22float2(*(const __half2*)&hidin[(size_t)r0*512 + hc]);
                    float2 f1 = __half22float2(*(const __half2*)&hidin[(size_t)(r0+8)*512 + hc]);
                    *(__half2*)&g_rf[(size_t)r0*512 + hc]     = __floats2half2_rn(s0*f0.x, s1*f0.y);
                    *(__half2*)&g_rf[(size_t)(r0+8)*512 + hc] = __floats2half2_rn(s2*f1.x, s3*f1.y);
                }
            } else if (ACT == ACT_RELU) {
                *(__half2*)&Ho[(size_t)r0*512 + gc]     = __floats2half2_rn(fmaxf(v0,0.f), fmaxf(v1,0.f));
                *(__half2*)&Ho[(size_t)(r0+8)*512 + gc] = __floats2half2_rn(fmaxf(v2,0.f), fmaxf(v3,0.f));
            } else {  // GRU
                float2 z0 = *(const float2*)&zbuf[(size_t)r0*512 + gc];
                float2 z1 = *(const float2*)&zbuf[(size_t)(r0+8)*512 + gc];
                float2 f0 = __half22float2(*(const __half2*)&hidin[(size_t)r0*512 + gc]);
                float2 f1 = __half22float2(*(const __half2*)&hidin[(size_t)(r0+8)*512 + gc]);
                float o0 = (1.f-z0.x)*f0.x + z0.x*tanhf(v0);
                float o1 = (1.f-z0.y)*f0.y + z0.y*tanhf(v1);
                float o2 = (1.f-z1.x)*f1.x + z1.x*tanhf(v2);
                float o3 = (1.f-z1.y)*f1.y + z1.y*tanhf(v3);
                *(__half2*)&Ho[(size_t)r0*512 + gc]     = __floats2half2_rn(o0, o1);
                *(__half2*)&Ho[(size_t)(r0+8)*512 + gc] = __floats2half2_rn(o2, o3);
            }
        }
    }
}

__global__ void k_reduce(const float* __restrict__ bc, float* __restrict__ out) {
    int i = blockIdx.x*blockDim.x + threadIdx.x;
    if (i >= R_*C_) return;
    float s = bc[i % C_];
    for (int z = 0; z < SPLITS_; ++z) s += g_part[(size_t)z*(R_*C_) + i];
    out[i] = s;
}

// ================= launch =================
extern "C" void kernel_launch(void* const* d_in, const int* in_sizes, int n_in,
                              void* d_out, int out_size) {
    const int*   sop    = (const int*)  d_in[1];
    const float* input  = (const float*)d_in[2];
    const float* matrix = (const float*)d_in[4];
    const float* w3w = (const float*)d_in[5];  const float* b3w = (const float*)d_in[6];
    const float* w3u = (const float*)d_in[7];  const float* b3u = (const float*)d_in[8];
    const float* w4w = (const float*)d_in[9];  const float* b4w = (const float*)d_in[10];
    const float* w4u = (const float*)d_in[11]; const float* b4u = (const float*)d_in[12];
    const float* w5w = (const float*)d_in[13]; const float* b5w = (const float*)d_in[14];
    const float* w5u = (const float*)d_in[15]; const float* b5u = (const float*)d_in[16];
    const float* wo  = (const float*)d_in[17]; const float* bo  = (const float*)d_in[18];
    const float* wc  = (const float*)d_in[19]; const float* bc  = (const float*)d_in[20];
    float* out = (float*)d_out;

    __half *p_h0, *p_h1, *p_inp, *p_sa, *p_rf, *p_out, *p_weff, *p_ucat, *p_wor, *p_wc;
    float  *p_Y, *p_z, *p_bias, *p_part;
    cudaGetSymbolAddress((void**)&p_h0,   g_hid0);
    cudaGetSymbolAddress((void**)&p_h1,   g_hid1);
    cudaGetSymbolAddress((void**)&p_inp,  g_inp);
    cudaGetSymbolAddress((void**)&p_sa,   g_sa);
    cudaGetSymbolAddress((void**)&p_rf,   g_rf);
    cudaGetSymbolAddress((void**)&p_out,  g_out);
    cudaGetSymbolAddress((void**)&p_weff, g_weff);
    cudaGetSymbolAddress((void**)&p_ucat, g_ucat);
    cudaGetSymbolAddress((void**)&p_wor,  g_wor);
    cudaGetSymbolAddress((void**)&p_wc,   g_wc);
    cudaGetSymbolAddress((void**)&p_Y,    g_Y);
    cudaGetSymbolAddress((void**)&p_z,    g_z);
    cudaGetSymbolAddress((void**)&p_bias, g_bias);
    cudaGetSymbolAddress((void**)&p_part, g_part);

    cudaFuncSetAttribute(k_hmma<ACT_NONE,1,false>, cudaFuncAttributeMaxDynamicSharedMemorySize, SMEM_BYTES);
    cudaFuncSetAttribute(k_hmma<ACT_NONE,1,true>,  cudaFuncAttributeMaxDynamicSharedMemorySize, SMEM_BYTES);
    cudaFuncSetAttribute(k_hmma<ACT_GATE,1,false>, cudaFuncAttributeMaxDynamicSharedMemorySize, SMEM_BYTES);
    cudaFuncSetAttribute(k_hmma<ACT_GRU,1,false>,  cudaFuncAttributeMaxDynamicSharedMemorySize, SMEM_BYTES);
    cudaFuncSetAttribute(k_hmma<ACT_RELU,2,false>, cudaFuncAttributeMaxDynamicSharedMemorySize, SMEM_BYTES);

    k_prep_all<<<(PREP_TOTAL_ + 255)/256, 256>>>(sop, matrix,
        w3w, w3u, b3w, b3u, w4w, w4u, b4w, b4u, w5w, w5u, b5w, b5u, wo, wc, input);

    dim3 gY   (1536/128, 4096/128);   // 12 x 32
    dim3 gGate(1024/128, RN_/128);    // 8 x 848
    dim3 gHv  (512/128,  RN_/128);    // 4 x 848
    dim3 gFin (1, R_/128, SPLITS_);   // 1 x 16 x 53

    __half* hin = p_inp;
    __half* houts[3] = {p_h0, p_h1, p_h0};
    for (int t = 0; t < T_; ++t) {
        __half* hout = houts[t];
        k_av<<<R_, 256>>>(hin);
        k_hmma<ACT_NONE,1,false><<<gY, 256, SMEM_BYTES>>>(
            p_sa, 512, p_weff, 512, nullptr, nullptr,
            nullptr, nullptr, nullptr, 0, p_Y, 1536, 1536, nullptr);
        k_hmma<ACT_GATE,1,false><<<gGate, 256, SMEM_BYTES>>>(
            hin, 512, p_ucat, 512, nullptr, nullptr,
            p_bias, hin, nullptr, 0, nullptr, 0, 0, nullptr);
        k_hmma<ACT_GRU,1,false><<<gHv, 256, SMEM_BYTES>>>(
            p_rf, 512, p_ucat + 2*H_*H_, 512, nullptr, nullptr,
            p_bias + 2*H_, hin, p_z, 1024, nullptr, 0, 0, hout);
        hin = hout;
    }

    k_hmma<ACT_RELU,2,false><<<gHv, 256, SMEM_BYTES>>>(
        hin, 512, p_wor, 512, p_inp, p_wor + H_*H_,
        bo, nullptr, nullptr, 0, nullptr, 0, 0, p_out);

    k_hmma<ACT_NONE,1,true><<<gFin, 256, SMEM_BYTES>>>(
        p_out, K2_, p_wc, K2_, nullptr, nullptr,
        nullptr, nullptr, nullptr, 0, p_part, C_, C_, nullptr);
    k_reduce<<<(R_*C_ + 255)/256, 256>>>(bc, out);
}

// round 13
// speedup vs baseline: 1.1032x; 1.0110x over previous
#include <cuda_runtime.h>
#include <cuda_fp16.h>
#include <math.h>
#include <stdint.h>

#define R_    2048
#define NODE_ 53
#define H_    512
#define C_    51
#define NOBJ_ 151
#define T_    3
#define RN_   (R_*NODE_)      /* 108544 */
#define K2_   (NODE_*512)     /* 27136  */
#define SPLITS_ 53

// ================= helpers =================
__device__ __forceinline__ void mma_f16(float* d, const uint32_t* a, const uint32_t* b) {
    asm volatile(
        "mma.sync.aligned.m16n8k16.row.col.f32.f16.f16.f32 "
        "{%0,%1,%2,%3}, {%4,%5,%6,%7}, {%8,%9}, {%0,%1,%2,%3};\n"
        : "+f"(d[0]), "+f"(d[1]), "+f"(d[2]), "+f"(d[3])
        : "r"(a[0]), "r"(a[1]), "r"(a[2]), "r"(a[3]), "r"(b[0]), "r"(b[1]));
}
__device__ __forceinline__ void ldsm4(uint32_t* r, uint32_t addr) {
    asm volatile("ldmatrix.sync.aligned.m8n8.x4.shared.b16 {%0,%1,%2,%3}, [%4];"
        : "=r"(r[0]), "=r"(r[1]), "=r"(r[2]), "=r"(r[3]) : "r"(addr));
}
__device__ __forceinline__ uint32_t smem_u32(const void* p) {
    uint32_t a;
    asm("{ .reg .u64 t; cvta.to.shared.u64 t, %1; cvt.u32.u64 %0, t; }" : "=r"(a) : "l"(p));
    return a;
}
__device__ __forceinline__ void cp_async16(uint32_t s, const void* g) {
    asm volatile("cp.async.cg.shared.global [%0], [%1], 16;" :: "r"(s), "l"(g));
}
#define CP_COMMIT() asm volatile("cp.async.commit_group;" ::: "memory")
#define CP_WAIT(n)  asm volatile("cp.async.wait_group %0;" :: "n"(n) : "memory")

// ================= scratch =================
__device__ __half g_hid0 [RN_*H_];
__device__ __half g_hid1 [RN_*H_];
__device__ __half g_inp  [RN_*H_];
__device__ __half g_sa   [2*R_*H_];
__device__ __half g_rf   [RN_*H_];
__device__ __half g_out  [RN_*H_];
__device__ __half g_z    [RN_*H_];       // zv fp16 (halves gate/GRU DRAM traffic)
__device__ __half g_weff [3*H_*H_];
__device__ __half g_ucat [3*H_*H_];
__device__ __half g_wor  [2*H_*H_];
__device__ __half g_wc   [128*K2_];
__device__ float  g_Y    [2*R_*3*H_];
__device__ float  g_bias [3*H_];
__device__ float  g_row  [R_*C_];
__device__ float  g_coef [RN_];
__device__ int    g_yrow [RN_];
__device__ float  g_part [SPLITS_*R_*C_];

// ========== combined prep (weights + metadata + input fp32->fp16) ==========
#define PREP_IN_  (RN_*H_/2)
#define PREP_W_   (3*H_*H_)
#define PREP_WO_  (2*H_*H_)
#define PREP_ROW_ (R_*C_)
#define PREP_CY_  (RN_)
#define PREP_WC_  (128*K2_)
#define PREP_TOTAL_ (PREP_IN_ + PREP_W_ + PREP_WO_ + PREP_ROW_ + PREP_CY_ + PREP_WC_)

__global__ void k_prep_all(
    const int* __restrict__ sop, const float* __restrict__ matrix,
    const float* w3w, const float* w3u, const float* b3w, const float* b3u,
    const float* w4w, const float* w4u, const float* b4w, const float* b4u,
    const float* w5w, const float* w5u, const float* b5w, const float* b5u,
    const float* __restrict__ wo, const float* __restrict__ wc,
    const float* __restrict__ input)
{
    int i = blockIdx.x*blockDim.x + threadIdx.x;
    if (i < PREP_IN_) {
        float2 v = ((const float2*)input)[i];
        ((__half2*)g_inp)[i] = __floats2half2_rn(v.x, v.y);
        return;
    }
    i -= PREP_IN_;
    if (i < PREP_W_) {
        int g = i / (H_*H_);
        int rem = i - g*(H_*H_);
        int h = rem / H_, k = rem - h*H_;
        const float* ww = (g==0) ? w3w : (g==1) ? w4w : w5w;
        const float* wu = (g==0) ? w3u : (g==1) ? w4u : w5u;
        g_weff[i] = __float2half_rn(ww[h*(2*H_) + k] + ww[h*(2*H_) + H_ + k]);
        g_ucat[i] = __float2half_rn(wu[rem]);
        if (i < 3*H_) {
            int gg = i / H_, h2 = i - gg*H_;
            const float* bw = (gg==0) ? b3w : (gg==1) ? b4w : b5w;
            const float* bu = (gg==0) ? b3u : (gg==1) ? b4u : b5u;
            g_bias[i] = bw[h2] + bu[h2];
        }
    } else if (i < PREP_W_ + PREP_WO_) {
        int j = i - PREP_W_;
        int row = j >> 10, col = j & 1023;
        int dst = (col < H_) ? row*H_ + col : (row + H_)*H_ + (col - H_);
        g_wor[dst] = __float2half_rn(wo[j]);
    } else if (i < PREP_W_ + PREP_WO_ + PREP_ROW_) {
        int j = i - PREP_W_ - PREP_WO_;
        int r = j / C_, c = j - r*C_;
        g_row[j] = matrix[((size_t)sop[2*r]*NOBJ_ + sop[2*r+1])*C_ + c];
    } else if (i < PREP_W_ + PREP_WO_ + PREP_ROW_ + PREP_CY_) {
        int j = i - PREP_W_ - PREP_WO_ - PREP_ROW_;
        int r = j / NODE_, e = j - r*NODE_;
        if (e < 2) { g_coef[j] = 1.f; g_yrow[j] = r; }
        else {
            g_coef[j] = matrix[((size_t)sop[2*r]*NOBJ_ + sop[2*r+1])*C_ + (e-2)];
            g_yrow[j] = R_ + r;
        }
    } else if (i < PREP_W_ + PREP_WO_ + PREP_ROW_ + PREP_CY_ + PREP_WC_) {
        int j = i - PREP_W_ - PREP_WO_ - PREP_ROW_ - PREP_CY_;
        int row = j / K2_, col = j - row*K2_;
        g_wc[j] = (row < C_) ? __float2half_rn(wc[(size_t)row*K2_ + col]) : __float2half_rn(0.f);
    }
}

// ================= av =================
__global__ void __launch_bounds__(256) k_av(const __half* __restrict__ hid) {
    __shared__ float srow[C_];
    int r = blockIdx.x;
    if (threadIdx.x < C_) srow[threadIdx.x] = g_row[r*C_ + threadIdx.x];
    __syncthreads();
    int h2i = threadIdx.x;
    const __half2* hb = (const __half2*)(hid + (size_t)r*NODE_*H_);
    float2 a0 = __half22float2(hb[h2i]);
    float2 a1 = __half22float2(hb[256 + h2i]);
    float sx = a0.x + a1.x, sy = a0.y + a1.y;
    float ax = 0.f, ay = 0.f;
    #pragma unroll 3
    for (int c = 0; c < C_; ++c) {
        float rc = srow[c];
        float2 v = __half22float2(hb[(2+c)*256 + h2i]);
        ax = fmaf(rc, v.x, ax);
        ay = fmaf(rc, v.y, ay);
    }
    __half2* sa = (__half2*)g_sa;
    sa[(size_t)r*256 + h2i]        = __floats2half2_rn(ax, ay);
    sa[(size_t)(R_+r)*256 + h2i]   = __floats2half2_rn(sx, sy);
}

// ===== fp16 mma GEMM: CTA 128x128, 8 warps (2x4), warp tile 64x32 ===========
#define ACT_NONE 0
#define ACT_GATE 1
#define ACT_GRU  2
#define ACT_RELU 3

#define ROWB_     144
#define STG_AB    (128*ROWB_)              /* 18432 */
#define STG_BYTES (2*STG_AB)               /* 36864 */
#define SMEM_BYTES (3*STG_BYTES)           /* 110592 */

template<int ACT, int NTERMS, bool SPLITK>
__global__ void __launch_bounds__(256, 2) k_hmma(
    const __half* __restrict__ A1, int lda1, const __half* __restrict__ W1, int ldw1,
    const __half* __restrict__ A2, const __half* __restrict__ W2,
    const float* __restrict__ bias,
    const __half* __restrict__ hidin,
    const __half* __restrict__ zbuf,   // GRU: zv fp16 (stride 512)
    int ycol0,
    float* __restrict__ Yco, int ldy, int nmax,
    __half* __restrict__ Ho)
{
    extern __shared__ __align__(16) char smc[];
    const uint32_t smem_base = smem_u32(smc);
    const int tid  = threadIdx.x;
    const int lane = tid & 31;
    const int wid  = tid >> 5;            // 0..7
    const int wm   = wid >> 2;            // 0..1
    const int wn   = wid & 3;             // 0..3
    const int blockRow = blockIdx.y * 128;
    const int blockCol = blockIdx.x * 128;
    const int kbeg = SPLITK ? blockIdx.z * 512 : 0;

    float acc[4][4][4];
    #pragma unroll
    for (int i = 0; i < 4; ++i)
        #pragma unroll
        for (int j = 0; j < 4; ++j)
            #pragma unroll
            for (int v = 0; v < 4; ++v) acc[i][j][v] = 0.f;

    const int mrow = tid >> 3;
    const int qk   = tid & 7;

    uint32_t aoff[4], boff[2];
    {
        const int rw = lane & 7;
        const int g1 = (lane >> 3) & 1;
        const int g2 = lane >> 4;
        #pragma unroll
        for (int i = 0; i < 4; ++i)
            aoff[i] = (uint32_t)(wm*64 + i*16 + rw + g1*8)*ROWB_ + g2*16;
        #pragma unroll
        for (int jj = 0; jj < 2; ++jj)
            boff[jj] = STG_AB + (uint32_t)(wn*32 + jj*16 + rw + g2*8)*ROWB_ + g1*16;
    }

    auto load_chunk = [&](int c, int stage) {
        const int term = c >> 3;
        const int kk0  = kbeg + (c & 7) * 64;
        const __half* A = term ? A2 : A1;  const int lda = term ? 512 : lda1;
        const __half* W = term ? W2 : W1;  const int ldw = term ? 512 : ldw1;
        const __half* Ag = A + (size_t)(blockRow + mrow)*lda + kk0 + qk*8;
        const __half* Wg = W + (size_t)(blockCol + mrow)*ldw + kk0 + qk*8;
        uint32_t sa = smem_base + stage*STG_BYTES + mrow*ROWB_ + qk*16;
        uint32_t sb = sa + STG_AB;
        #pragma unroll
        for (int p = 0; p < 4; ++p) {
            cp_async16(sa + p*32*ROWB_, Ag + (size_t)p*32*lda);
            cp_async16(sb + p*32*ROWB_, Wg + (size_t)p*32*ldw);
        }
    };

    auto compute = [&](int stage) {
        const uint32_t sbase = smem_base + stage*STG_BYTES;
        #pragma unroll
        for (int s = 0; s < 4; ++s) {
            uint32_t af[4][4], bf[2][4];
            #pragma unroll
            for (int i = 0; i < 4; ++i)   ldsm4(af[i],  sbase + aoff[i]  + s*32);
            #pragma unroll
            for (int jj = 0; jj < 2; ++jj) ldsm4(bf[jj], sbase + boff[jj] + s*32);
            #pragma unroll
            for (int i = 0; i < 4; ++i)
                #pragma unroll
                for (int jj = 0; jj < 2; ++jj) {
                    mma_f16(acc[i][2*jj],   af[i], &bf[jj][0]);
                    mma_f16(acc[i][2*jj+1], af[i], &bf[jj][2]);
                }
        }
    };

    const int NCH = 8*NTERMS;
    load_chunk(0, 0); CP_COMMIT();
    load_chunk(1, 1); CP_COMMIT();

    int stage_n = 2;
    for (int c = 0; c < NCH; ++c) {
        CP_WAIT(1);
        __syncthreads();
        if (c + 2 < NCH) load_chunk(c + 2, stage_n);
        CP_COMMIT();
        int stage_c = stage_n + 1; if (stage_c >= 3) stage_c -= 3;
        compute(stage_c);
        stage_n = stage_c;
    }
    CP_WAIT(0);

    // ---- epilogue
    const size_t zoff = SPLITK ? (size_t)blockIdx.z * (R_*C_) : 0;
    #pragma unroll
    for (int i = 0; i < 4; ++i) {
        const int r0 = blockRow + wm*64 + i*16 + (lane >> 2);
        float cf0 = 0.f, cf1 = 0.f;
        const float *y0p = nullptr, *y1p = nullptr;
        if (ACT == ACT_GATE || ACT == ACT_GRU) {
            cf0 = g_coef[r0];     y0p = g_Y + (size_t)g_yrow[r0]*1536   + ycol0;
            cf1 = g_coef[r0+8];   y1p = g_Y + (size_t)g_yrow[r0+8]*1536 + ycol0;
        }
        #pragma unroll
        for (int j = 0; j < 4; ++j) {
            const int gc = blockCol + wn*32 + j*8 + (lane & 3)*2;
            float v0 = acc[i][j][0];
            float v1 = acc[i][j][1];
            float v2 = acc[i][j][2];
            float v3 = acc[i][j][3];
            if (ACT != ACT_NONE) {
                float2 bs = *(const float2*)&bias[gc];
                v0 += bs.x; v1 += bs.y; v2 += bs.x; v3 += bs.y;
            }
            if (ACT == ACT_GATE || ACT == ACT_GRU) {
                float2 y0 = *(const float2*)&y0p[gc];
                float2 y1 = *(const float2*)&y1p[gc];
                v0 = fmaf(cf0, y0.x, v0); v1 = fmaf(cf0, y0.y, v1);
                v2 = fmaf(cf1, y1.x, v2); v3 = fmaf(cf1, y1.y, v3);
            }
            if (ACT == ACT_NONE) {
                if (SPLITK) {
                    if (gc < nmax) {
                        Yco[zoff + (size_t)r0*ldy + gc]     = v0;
                        Yco[zoff + (size_t)(r0+8)*ldy + gc] = v2;
                    }
                    if (gc + 1 < nmax) {
                        Yco[zoff + (size_t)r0*ldy + gc + 1]     = v1;
                        Yco[zoff + (size_t)(r0+8)*ldy + gc + 1] = v3;
                    }
                } else {
                    *(float2*)&Yco[(size_t)r0*ldy + gc]     = make_float2(v0, v1);
                    *(float2*)&Yco[(size_t)(r0+8)*ldy + gc] = make_float2(v2, v3);
                }
            } else if (ACT == ACT_GATE) {
                float s0 = 1.f/(1.f+__expf(-v0)), s1 = 1.f/(1.f+__expf(-v1));
                float s2 = 1.f/(1.f+__expf(-v2)), s3 = 1.f/(1.f+__expf(-v3));
                if (gc < 512) {   // z half -> fp16 z buffer
                    *(__half2*)&g_z[(size_t)r0*512 + gc]     = __floats2half2_rn(s0, s1);
                    *(__half2*)&g_z[(size_t)(r0+8)*512 + gc] = __floats2half2_rn(s2, s3);
                } else {          // r half -> rf = half(r * f)
                    const int hc = gc - 512;
                    float2 f0 = __half22float2(*(const __half2*)&hidin[(size_t)r0*512 + hc]);
                    float2 f1 = __half22float2(*(const __half2*)&hidin[(size_t)(r0+8)*512 + hc]);
                    *(__half2*)&g_rf[(size_t)r0*512 + hc]     = __floats2half2_rn(s0*f0.x, s1*f0.y);
                    *(__half2*)&g_rf[(size_t)(r0+8)*512 + hc] = __floats2half2_rn(s2*f1.x, s3*f1.y);
                }
            } else if (ACT == ACT_RELU) {
                *(__half2*)&Ho[(size_t)r0*512 + gc]     = __floats2half2_rn(fmaxf(v0,0.f), fmaxf(v1,0.f));
                *(__half2*)&Ho[(size_t)(r0+8)*512 + gc] = __floats2half2_rn(fmaxf(v2,0.f), fmaxf(v3,0.f));
            } else {  // GRU: h' = (1-z)*f + z*tanh(v)
                float2 z0 = __half22float2(*(const __half2*)&zbuf[(size_t)r0*512 + gc]);
                float2 z1 = __half22float2(*(const __half2*)&zbuf[(size_t)(r0+8)*512 + gc]);
                float2 f0 = __half22float2(*(const __half2*)&hidin[(size_t)r0*512 + gc]);
                float2 f1 = __half22float2(*(const __half2*)&hidin[(size_t)(r0+8)*512 + gc]);
                float o0 = (1.f-z0.x)*f0.x + z0.x*tanhf(v0);
                float o1 = (1.f-z0.y)*f0.y + z0.y*tanhf(v1);
                float o2 = (1.f-z1.x)*f1.x + z1.x*tanhf(v2);
                float o3 = (1.f-z1.y)*f1.y + z1.y*tanhf(v3);
                *(__half2*)&Ho[(size_t)r0*512 + gc]     = __floats2half2_rn(o0, o1);
                *(__half2*)&Ho[(size_t)(r0+8)*512 + gc] = __floats2half2_rn(o2, o3);
            }
        }
    }
}

__global__ void k_reduce(const float* __restrict__ bc, float* __restrict__ out) {
    int i = blockIdx.x*blockDim.x + threadIdx.x;
    if (i >= R_*C_) return;
    float s = bc[i % C_];
    for (int z = 0; z < SPLITS_; ++z) s += g_part[(size_t)z*(R_*C_) + i];
    out[i] = s;
}

// ================= launch =================
extern "C" void kernel_launch(void* const* d_in, const int* in_sizes, int n_in,
                              void* d_out, int out_size) {
    const int*   sop    = (const int*)  d_in[1];
    const float* input  = (const float*)d_in[2];
    const float* matrix = (const float*)d_in[4];
    const float* w3w = (const float*)d_in[5];  const float* b3w = (const float*)d_in[6];
    const float* w3u = (const float*)d_in[7];  const float* b3u = (const float*)d_in[8];
    const float* w4w = (const float*)d_in[9];  const float* b4w = (const float*)d_in[10];
    const float* w4u = (const float*)d_in[11]; const float* b4u = (const float*)d_in[12];
    const float* w5w = (const float*)d_in[13]; const float* b5w = (const float*)d_in[14];
    const float* w5u = (const float*)d_in[15]; const float* b5u = (const float*)d_in[16];
    const float* wo  = (const float*)d_in[17]; const float* bo  = (const float*)d_in[18];
    const float* wc  = (const float*)d_in[19]; const float* bc  = (const float*)d_in[20];
    float* out = (float*)d_out;

    __half *p_h0, *p_h1, *p_inp, *p_sa, *p_rf, *p_out, *p_z, *p_weff, *p_ucat, *p_wor, *p_wc;
    float  *p_Y, *p_bias, *p_part;
    cudaGetSymbolAddress((void**)&p_h0,   g_hid0);
    cudaGetSymbolAddress((void**)&p_h1,   g_hid1);
    cudaGetSymbolAddress((void**)&p_inp,  g_inp);
    cudaGetSymbolAddress((void**)&p_sa,   g_sa);
    cudaGetSymbolAddress((void**)&p_rf,   g_rf);
    cudaGetSymbolAddress((void**)&p_out,  g_out);
    cudaGetSymbolAddress((void**)&p_z,    g_z);
    cudaGetSymbolAddress((void**)&p_weff, g_weff);
    cudaGetSymbolAddress((void**)&p_ucat, g_ucat);
    cudaGetSymbolAddress((void**)&p_wor,  g_wor);
    cudaGetSymbolAddress((void**)&p_wc,   g_wc);
    cudaGetSymbolAddress((void**)&p_Y,    g_Y);
    cudaGetSymbolAddress((void**)&p_bias, g_bias);
    cudaGetSymbolAddress((void**)&p_part, g_part);

    cudaFuncSetAttribute(k_hmma<ACT_NONE,1,false>, cudaFuncAttributeMaxDynamicSharedMemorySize, SMEM_BYTES);
    cudaFuncSetAttribute(k_hmma<ACT_NONE,1,true>,  cudaFuncAttributeMaxDynamicSharedMemorySize, SMEM_BYTES);
    cudaFuncSetAttribute(k_hmma<ACT_GATE,1,false>, cudaFuncAttributeMaxDynamicSharedMemorySize, SMEM_BYTES);
    cudaFuncSetAttribute(k_hmma<ACT_GRU,1,false>,  cudaFuncAttributeMaxDynamicSharedMemorySize, SMEM_BYTES);
    cudaFuncSetAttribute(k_hmma<ACT_RELU,2,false>, cudaFuncAttributeMaxDynamicSharedMemorySize, SMEM_BYTES);

    k_prep_all<<<(PREP_TOTAL_ + 255)/256, 256>>>(sop, matrix,
        w3w, w3u, b3w, b3u, w4w, w4u, b4w, b4u, w5w, w5u, b5w, b5u, wo, wc, input);

    dim3 gY   (1536/128, 4096/128);   // 12 x 32
    dim3 gGate(1024/128, RN_/128);    // 8 x 848
    dim3 gHv  (512/128,  RN_/128);    // 4 x 848
    dim3 gFin (1, R_/128, SPLITS_);   // 1 x 16 x 53

    __half* hin = p_inp;
    __half* houts[3] = {p_h0, p_h1, p_h0};
    for (int t = 0; t < T_; ++t) {
        __half* hout = houts[t];
        k_av<<<R_, 256>>>(hin);
        k_hmma<ACT_NONE,1,false><<<gY, 256, SMEM_BYTES>>>(
            p_sa, 512, p_weff, 512, nullptr, nullptr,
            nullptr, nullptr, nullptr, 0, p_Y, 1536, 1536, nullptr);
        k_hmma<ACT_GATE,1,false><<<gGate, 256, SMEM_BYTES>>>(
            hin, 512, p_ucat, 512, nullptr, nullptr,
            p_bias, hin, nullptr, 0, nullptr, 0, 0, nullptr);
        k_hmma<ACT_GRU,1,false><<<gHv, 256, SMEM_BYTES>>>(
            p_rf, 512, p_ucat + 2*H_*H_, 512, nullptr, nullptr,
            p_bias + 2*H_, hin, p_z, 1024, nullptr, 0, 0, hout);
        hin = hout;
    }

    k_hmma<ACT_RELU,2,false><<<gHv, 256, SMEM_BYTES>>>(
        hin, 512, p_wor, 512, p_inp, p_wor + H_*H_,
        bo, nullptr, nullptr, 0, nullptr, 0, 0, p_out);

    k_hmma<ACT_NONE,1,true><<<gFin, 256, SMEM_BYTES>>>(
        p_out, K2_, p_wc, K2_, nullptr, nullptr,
        nullptr, nullptr, nullptr, 0, p_part, C_, C_, nullptr);
    k_reduce<<<(R_*C_ + 255)/256, 256>>>(bc, out);
}

// round 14
// speedup vs baseline: 1.1953x; 1.0834x over previous
#include <cuda_runtime.h>
#include <cuda_fp16.h>
#include <math.h>
#include <stdint.h>

#define R_    2048
#define NODE_ 53
#define H_    512
#define C_    51
#define NOBJ_ 151
#define T_    3
#define RN_   (R_*NODE_)      /* 108544 */
#define K2_   (NODE_*512)     /* 27136  */
#define SPLITS_ 53

// ================= helpers =================
__device__ __forceinline__ void mma_f16(float* d, const uint32_t* a, const uint32_t* b) {
    asm volatile(
        "mma.sync.aligned.m16n8k16.row.col.f32.f16.f16.f32 "
        "{%0,%1,%2,%3}, {%4,%5,%6,%7}, {%8,%9}, {%0,%1,%2,%3};\n"
        : "+f"(d[0]), "+f"(d[1]), "+f"(d[2]), "+f"(d[3])
        : "r"(a[0]), "r"(a[1]), "r"(a[2]), "r"(a[3]), "r"(b[0]), "r"(b[1]));
}
__device__ __forceinline__ void ldsm4(uint32_t* r, uint32_t addr) {
    asm volatile("ldmatrix.sync.aligned.m8n8.x4.shared.b16 {%0,%1,%2,%3}, [%4];"
        : "=r"(r[0]), "=r"(r[1]), "=r"(r[2]), "=r"(r[3]) : "r"(addr));
}
__device__ __forceinline__ uint32_t smem_u32(const void* p) {
    uint32_t a;
    asm("{ .reg .u64 t; cvta.to.shared.u64 t, %1; cvt.u32.u64 %0, t; }" : "=r"(a) : "l"(p));
    return a;
}
__device__ __forceinline__ void cp_async16(uint32_t s, const void* g) {
    asm volatile("cp.async.cg.shared.global [%0], [%1], 16;" :: "r"(s), "l"(g));
}
#define CP_COMMIT() asm volatile("cp.async.commit_group;" ::: "memory")
#define CP_WAIT(n)  asm volatile("cp.async.wait_group %0;" :: "n"(n) : "memory")

// fast sigmoid / tanh via MUFU (ex2 + rcp); rel err ~1e-6, correct saturation
__device__ __forceinline__ float fsig(float v)  { return __fdividef(1.f, 1.f + __expf(-v)); }
__device__ __forceinline__ float ftanh(float v) { return 1.f - __fdividef(2.f, __expf(2.f*v) + 1.f); }

// ================= scratch =================
__device__ __half g_hid0 [RN_*H_];
__device__ __half g_hid1 [RN_*H_];
__device__ __half g_inp  [RN_*H_];
__device__ __half g_sa   [2*R_*H_];
__device__ __half g_rf   [RN_*H_];
__device__ __half g_out  [RN_*H_];
__device__ __half g_z    [RN_*H_];       // zv fp16
__device__ __half g_weff [3*H_*H_];
__device__ __half g_ucat [3*H_*H_];
__device__ __half g_wor  [2*H_*H_];
__device__ __half g_wc   [128*K2_];
__device__ float  g_Y    [2*R_*3*H_];
__device__ float  g_bias [3*H_];
__device__ float  g_row  [R_*C_];
__device__ float  g_coef [RN_];
__device__ int    g_yrow [RN_];
__device__ float  g_part [SPLITS_*R_*C_];

// ========== combined prep (weights + metadata + input fp32->fp16) ==========
#define PREP_IN_  (RN_*H_/2)
#define PREP_W_   (3*H_*H_)
#define PREP_WO_  (2*H_*H_)
#define PREP_ROW_ (R_*C_)
#define PREP_CY_  (RN_)
#define PREP_WC_  (128*K2_)
#define PREP_TOTAL_ (PREP_IN_ + PREP_W_ + PREP_WO_ + PREP_ROW_ + PREP_CY_ + PREP_WC_)

__global__ void k_prep_all(
    const int* __restrict__ sop, const float* __restrict__ matrix,
    const float* w3w, const float* w3u, const float* b3w, const float* b3u,
    const float* w4w, const float* w4u, const float* b4w, const float* b4u,
    const float* w5w, const float* w5u, const float* b5w, const float* b5u,
    const float* __restrict__ wo, const float* __restrict__ wc,
    const float* __restrict__ input)
{
    int i = blockIdx.x*blockDim.x + threadIdx.x;
    if (i < PREP_IN_) {
        float2 v = ((const float2*)input)[i];
        ((__half2*)g_inp)[i] = __floats2half2_rn(v.x, v.y);
        return;
    }
    i -= PREP_IN_;
    if (i < PREP_W_) {
        int g = i / (H_*H_);
        int rem = i - g*(H_*H_);
        int h = rem / H_, k = rem - h*H_;
        const float* ww = (g==0) ? w3w : (g==1) ? w4w : w5w;
        const float* wu = (g==0) ? w3u : (g==1) ? w4u : w5u;
        g_weff[i] = __float2half_rn(ww[h*(2*H_) + k] + ww[h*(2*H_) + H_ + k]);
        g_ucat[i] = __float2half_rn(wu[rem]);
        if (i < 3*H_) {
            int gg = i / H_, h2 = i - gg*H_;
            const float* bw = (gg==0) ? b3w : (gg==1) ? b4w : b5w;
            const float* bu = (gg==0) ? b3u : (gg==1) ? b4u : b5u;
            g_bias[i] = bw[h2] + bu[h2];
        }
    } else if (i < PREP_W_ + PREP_WO_) {
        int j = i - PREP_W_;
        int row = j >> 10, col = j & 1023;
        int dst = (col < H_) ? row*H_ + col : (row + H_)*H_ + (col - H_);
        g_wor[dst] = __float2half_rn(wo[j]);
    } else if (i < PREP_W_ + PREP_WO_ + PREP_ROW_) {
        int j = i - PREP_W_ - PREP_WO_;
        int r = j / C_, c = j - r*C_;
        g_row[j] = matrix[((size_t)sop[2*r]*NOBJ_ + sop[2*r+1])*C_ + c];
    } else if (i < PREP_W_ + PREP_WO_ + PREP_ROW_ + PREP_CY_) {
        int j = i - PREP_W_ - PREP_WO_ - PREP_ROW_;
        int r = j / NODE_, e = j - r*NODE_;
        if (e < 2) { g_coef[j] = 1.f; g_yrow[j] = r; }
        else {
            g_coef[j] = matrix[((size_t)sop[2*r]*NOBJ_ + sop[2*r+1])*C_ + (e-2)];
            g_yrow[j] = R_ + r;
        }
    } else if (i < PREP_W_ + PREP_WO_ + PREP_ROW_ + PREP_CY_ + PREP_WC_) {
        int j = i - PREP_W_ - PREP_WO_ - PREP_ROW_ - PREP_CY_;
        int row = j / K2_, col = j - row*K2_;
        g_wc[j] = (row < C_) ? __float2half_rn(wc[(size_t)row*K2_ + col]) : __float2half_rn(0.f);
    }
}

// ================= av =================
__global__ void __launch_bounds__(256) k_av(const __half* __restrict__ hid) {
    __shared__ float srow[C_];
    int r = blockIdx.x;
    if (threadIdx.x < C_) srow[threadIdx.x] = g_row[r*C_ + threadIdx.x];
    __syncthreads();
    int h2i = threadIdx.x;
    const __half2* hb = (const __half2*)(hid + (size_t)r*NODE_*H_);
    float2 a0 = __half22float2(hb[h2i]);
    float2 a1 = __half22float2(hb[256 + h2i]);
    float sx = a0.x + a1.x, sy = a0.y + a1.y;
    float ax = 0.f, ay = 0.f;
    #pragma unroll 3
    for (int c = 0; c < C_; ++c) {
        float rc = srow[c];
        float2 v = __half22float2(hb[(2+c)*256 + h2i]);
        ax = fmaf(rc, v.x, ax);
        ay = fmaf(rc, v.y, ay);
    }
    __half2* sa = (__half2*)g_sa;
    sa[(size_t)r*256 + h2i]        = __floats2half2_rn(ax, ay);
    sa[(size_t)(R_+r)*256 + h2i]   = __floats2half2_rn(sx, sy);
}

// ===== fp16 mma GEMM: CTA 128x128, 8 warps (2x4), warp tile 64x32 ===========
#define ACT_NONE 0
#define ACT_GATE 1
#define ACT_GRU  2
#define ACT_RELU 3

#define ROWB_     144
#define STG_AB    (128*ROWB_)              /* 18432 */
#define STG_BYTES (2*STG_AB)               /* 36864 */
#define SMEM_BYTES (3*STG_BYTES)           /* 110592 */

template<int ACT, int NTERMS, bool SPLITK>
__global__ void __launch_bounds__(256, 2) k_hmma(
    const __half* __restrict__ A1, int lda1, const __half* __restrict__ W1, int ldw1,
    const __half* __restrict__ A2, const __half* __restrict__ W2,
    const float* __restrict__ bias,
    const __half* __restrict__ hidin,
    const __half* __restrict__ zbuf,   // GRU: zv fp16 (stride 512)
    int ycol0,
    float* __restrict__ Yco, int ldy, int nmax,
    __half* __restrict__ Ho)
{
    extern __shared__ __align__(16) char smc[];
    const uint32_t smem_base = smem_u32(smc);
    const int tid  = threadIdx.x;
    const int lane = tid & 31;
    const int wid  = tid >> 5;            // 0..7
    const int wm   = wid >> 2;            // 0..1
    const int wn   = wid & 3;             // 0..3
    const int blockRow = blockIdx.y * 128;
    const int blockCol = blockIdx.x * 128;
    const int kbeg = SPLITK ? blockIdx.z * 512 : 0;

    float acc[4][4][4];
    #pragma unroll
    for (int i = 0; i < 4; ++i)
        #pragma unroll
        for (int j = 0; j < 4; ++j)
            #pragma unroll
            for (int v = 0; v < 4; ++v) acc[i][j][v] = 0.f;

    const int mrow = tid >> 3;
    const int qk   = tid & 7;

    uint32_t aoff[4], boff[2];
    {
        const int rw = lane & 7;
        const int g1 = (lane >> 3) & 1;
        const int g2 = lane >> 4;
        #pragma unroll
        for (int i = 0; i < 4; ++i)
            aoff[i] = (uint32_t)(wm*64 + i*16 + rw + g1*8)*ROWB_ + g2*16;
        #pragma unroll
        for (int jj = 0; jj < 2; ++jj)
            boff[jj] = STG_AB + (uint32_t)(wn*32 + jj*16 + rw + g2*8)*ROWB_ + g1*16;
    }

    auto load_chunk = [&](int c, int stage) {
        const int term = c >> 3;
        const int kk0  = kbeg + (c & 7) * 64;
        const __half* A = term ? A2 : A1;  const int lda = term ? 512 : lda1;
        const __half* W = term ? W2 : W1;  const int ldw = term ? 512 : ldw1;
        const __half* Ag = A + (size_t)(blockRow + mrow)*lda + kk0 + qk*8;
        const __half* Wg = W + (size_t)(blockCol + mrow)*ldw + kk0 + qk*8;
        uint32_t sa = smem_base + stage*STG_BYTES + mrow*ROWB_ + qk*16;
        uint32_t sb = sa + STG_AB;
        #pragma unroll
        for (int p = 0; p < 4; ++p) {
            cp_async16(sa + p*32*ROWB_, Ag + (size_t)p*32*lda);
            cp_async16(sb + p*32*ROWB_, Wg + (size_t)p*32*ldw);
        }
    };

    auto compute = [&](int stage) {
        const uint32_t sbase = smem_base + stage*STG_BYTES;
        #pragma unroll
        for (int s = 0; s < 4; ++s) {
            uint32_t af[4][4], bf[2][4];
            #pragma unroll
            for (int i = 0; i < 4; ++i)   ldsm4(af[i],  sbase + aoff[i]  + s*32);
            #pragma unroll
            for (int jj = 0; jj < 2; ++jj) ldsm4(bf[jj], sbase + boff[jj] + s*32);
            #pragma unroll
            for (int i = 0; i < 4; ++i)
                #pragma unroll
                for (int jj = 0; jj < 2; ++jj) {
                    mma_f16(acc[i][2*jj],   af[i], &bf[jj][0]);
                    mma_f16(acc[i][2*jj+1], af[i], &bf[jj][2]);
                }
        }
    };

    const int NCH = 8*NTERMS;
    load_chunk(0, 0); CP_COMMIT();
    load_chunk(1, 1); CP_COMMIT();

    int stage_n = 2;
    for (int c = 0; c < NCH; ++c) {
        CP_WAIT(1);
        __syncthreads();
        if (c + 2 < NCH) load_chunk(c + 2, stage_n);
        CP_COMMIT();
        int stage_c = stage_n + 1; if (stage_c >= 3) stage_c -= 3;
        compute(stage_c);
        stage_n = stage_c;
    }
    CP_WAIT(0);

    // ---- epilogue
    const size_t zoff = SPLITK ? (size_t)blockIdx.z * (R_*C_) : 0;
    #pragma unroll
    for (int i = 0; i < 4; ++i) {
        const int r0 = blockRow + wm*64 + i*16 + (lane >> 2);
        float cf0 = 0.f, cf1 = 0.f;
        const float *y0p = nullptr, *y1p = nullptr;
        if (ACT == ACT_GATE || ACT == ACT_GRU) {
            cf0 = g_coef[r0];     y0p = g_Y + (size_t)g_yrow[r0]*1536   + ycol0;
            cf1 = g_coef[r0+8];   y1p = g_Y + (size_t)g_yrow[r0+8]*1536 + ycol0;
        }
        #pragma unroll
        for (int j = 0; j < 4; ++j) {
            const int gc = blockCol + wn*32 + j*8 + (lane & 3)*2;
            float v0 = acc[i][j][0];
            float v1 = acc[i][j][1];
            float v2 = acc[i][j][2];
            float v3 = acc[i][j][3];
            if (ACT != ACT_NONE) {
                float2 bs = *(const float2*)&bias[gc];
                v0 += bs.x; v1 += bs.y; v2 += bs.x; v3 += bs.y;
            }
            if (ACT == ACT_GATE || ACT == ACT_GRU) {
                float2 y0 = *(const float2*)&y0p[gc];
                float2 y1 = *(const float2*)&y1p[gc];
                v0 = fmaf(cf0, y0.x, v0); v1 = fmaf(cf0, y0.y, v1);
                v2 = fmaf(cf1, y1.x, v2); v3 = fmaf(cf1, y1.y, v3);
            }
            if (ACT == ACT_NONE) {
                if (SPLITK) {
                    if (gc < nmax) {
                        Yco[zoff + (size_t)r0*ldy + gc]     = v0;
                        Yco[zoff + (size_t)(r0+8)*ldy + gc] = v2;
                    }
                    if (gc + 1 < nmax) {
                        Yco[zoff + (size_t)r0*ldy + gc + 1]     = v1;
                        Yco[zoff + (size_t)(r0+8)*ldy + gc + 1] = v3;
                    }
                } else {
                    *(float2*)&Yco[(size_t)r0*ldy + gc]     = make_float2(v0, v1);
                    *(float2*)&Yco[(size_t)(r0+8)*ldy + gc] = make_float2(v2, v3);
                }
            } else if (ACT == ACT_GATE) {
                float s0 = fsig(v0), s1 = fsig(v1);
                float s2 = fsig(v2), s3 = fsig(v3);
                if (gc < 512) {   // z half -> fp16 z buffer
                    *(__half2*)&g_z[(size_t)r0*512 + gc]     = __floats2half2_rn(s0, s1);
                    *(__half2*)&g_z[(size_t)(r0+8)*512 + gc] = __floats2half2_rn(s2, s3);
                } else {          // r half -> rf = half(r * f)
                    const int hc = gc - 512;
                    float2 f0 = __half22float2(*(const __half2*)&hidin[(size_t)r0*512 + hc]);
                    float2 f1 = __half22float2(*(const __half2*)&hidin[(size_t)(r0+8)*512 + hc]);
                    *(__half2*)&g_rf[(size_t)r0*512 + hc]     = __floats2half2_rn(s0*f0.x, s1*f0.y);
                    *(__half2*)&g_rf[(size_t)(r0+8)*512 + hc] = __floats2half2_rn(s2*f1.x, s3*f1.y);
                }
            } else if (ACT == ACT_RELU) {
                *(__half2*)&Ho[(size_t)r0*512 + gc]     = __floats2half2_rn(fmaxf(v0,0.f), fmaxf(v1,0.f));
                *(__half2*)&Ho[(size_t)(r0+8)*512 + gc] = __floats2half2_rn(fmaxf(v2,0.f), fmaxf(v3,0.f));
            } else {  // GRU: h' = (1-z)*f + z*tanh(v)
                float2 z0 = __half22float2(*(const __half2*)&zbuf[(size_t)r0*512 + gc]);
                float2 z1 = __half22float2(*(const __half2*)&zbuf[(size_t)(r0+8)*512 + gc]);
                float2 f0 = __half22float2(*(const __half2*)&hidin[(size_t)r0*512 + gc]);
                float2 f1 = __half22float2(*(const __half2*)&hidin[(size_t)(r0+8)*512 + gc]);
                float o0 = (1.f-z0.x)*f0.x + z0.x*ftanh(v0);
                float o1 = (1.f-z0.y)*f0.y + z0.y*ftanh(v1);
                float o2 = (1.f-z1.x)*f1.x + z1.x*ftanh(v2);
                float o3 = (1.f-z1.y)*f1.y + z1.y*ftanh(v3);
                *(__half2*)&Ho[(size_t)r0*512 + gc]     = __floats2half2_rn(o0, o1);
                *(__half2*)&Ho[(size_t)(r0+8)*512 + gc] = __floats2half2_rn(o2, o3);
            }
        }
    }
}

__global__ void k_reduce(const float* __restrict__ bc, float* __restrict__ out) {
    int i = blockIdx.x*blockDim.x + threadIdx.x;
    if (i >= R_*C_) return;
    float s = bc[i % C_];
    for (int z = 0; z < SPLITS_; ++z) s += g_part[(size_t)z*(R_*C_) + i];
    out[i] = s;
}

// ================= launch =================
extern "C" void kernel_launch(void* const* d_in, const int* in_sizes, int n_in,
                              void* d_out, int out_size) {
    const int*   sop    = (const int*)  d_in[1];
    const float* input  = (const float*)d_in[2];
    const float* matrix = (const float*)d_in[4];
    const float* w3w = (const float*)d_in[5];  const float* b3w = (const float*)d_in[6];
    const float* w3u = (const float*)d_in[7];  const float* b3u = (const float*)d_in[8];
    const float* w4w = (const float*)d_in[9];  const float* b4w = (const float*)d_in[10];
    const float* w4u = (const float*)d_in[11]; const float* b4u = (const float*)d_in[12];
    const float* w5w = (const float*)d_in[13]; const float* b5w = (const float*)d_in[14];
    const float* w5u = (const float*)d_in[15]; const float* b5u = (const float*)d_in[16];
    const float* wo  = (const float*)d_in[17]; const float* bo  = (const float*)d_in[18];
    const float* wc  = (const float*)d_in[19]; const float* bc  = (const float*)d_in[20];
    float* out = (float*)d_out;

    __half *p_h0, *p_h1, *p_inp, *p_sa, *p_rf, *p_out, *p_z, *p_weff, *p_ucat, *p_wor, *p_wc;
    float  *p_Y, *p_bias, *p_part;
    cudaGetSymbolAddress((void**)&p_h0,   g_hid0);
    cudaGetSymbolAddress((void**)&p_h1,   g_hid1);
    cudaGetSymbolAddress((void**)&p_inp,  g_inp);
    cudaGetSymbolAddress((void**)&p_sa,   g_sa);
    cudaGetSymbolAddress((void**)&p_rf,   g_rf);
    cudaGetSymbolAddress((void**)&p_out,  g_out);
    cudaGetSymbolAddress((void**)&p_z,    g_z);
    cudaGetSymbolAddress((void**)&p_weff, g_weff);
    cudaGetSymbolAddress((void**)&p_ucat, g_ucat);
    cudaGetSymbolAddress((void**)&p_wor,  g_wor);
    cudaGetSymbolAddress((void**)&p_wc,   g_wc);
    cudaGetSymbolAddress((void**)&p_Y,    g_Y);
    cudaGetSymbolAddress((void**)&p_bias, g_bias);
    cudaGetSymbolAddress((void**)&p_part, g_part);

    cudaFuncSetAttribute(k_hmma<ACT_NONE,1,false>, cudaFuncAttributeMaxDynamicSharedMemorySize, SMEM_BYTES);
    cudaFuncSetAttribute(k_hmma<ACT_NONE,1,true>,  cudaFuncAttributeMaxDynamicSharedMemorySize, SMEM_BYTES);
    cudaFuncSetAttribute(k_hmma<ACT_GATE,1,false>, cudaFuncAttributeMaxDynamicSharedMemorySize, SMEM_BYTES);
    cudaFuncSetAttribute(k_hmma<ACT_GRU,1,false>,  cudaFuncAttributeMaxDynamicSharedMemorySize, SMEM_BYTES);
    cudaFuncSetAttribute(k_hmma<ACT_RELU,2,false>, cudaFuncAttributeMaxDynamicSharedMemorySize, SMEM_BYTES);

    k_prep_all<<<(PREP_TOTAL_ + 255)/256, 256>>>(sop, matrix,
        w3w, w3u, b3w, b3u, w4w, w4u, b4w, b4u, w5w, w5u, b5w, b5u, wo, wc, input);

    dim3 gY   (1536/128, 4096/128);   // 12 x 32
    dim3 gGate(1024/128, RN_/128);    // 8 x 848
    dim3 gHv  (512/128,  RN_/128);    // 4 x 848
    dim3 gFin (1, R_/128, SPLITS_);   // 1 x 16 x 53

    __half* hin = p_inp;
    __half* houts[3] = {p_h0, p_h1, p_h0};
    for (int t = 0; t < T_; ++t) {
        __half* hout = houts[t];
        k_av<<<R_, 256>>>(hin);
        k_hmma<ACT_NONE,1,false><<<gY, 256, SMEM_BYTES>>>(
            p_sa, 512, p_weff, 512, nullptr, nullptr,
            nullptr, nullptr, nullptr, 0, p_Y, 1536, 1536, nullptr);
        k_hmma<ACT_GATE,1,false><<<gGate, 256, SMEM_BYTES>>>(
            hin, 512, p_ucat, 512, nullptr, nullptr,
            p_bias, hin, nullptr, 0, nullptr, 0, 0, nullptr);
        k_hmma<ACT_GRU,1,false><<<gHv, 256, SMEM_BYTES>>>(
            p_rf, 512, p_ucat + 2*H_*H_, 512, nullptr, nullptr,
            p_bias + 2*H_, hin, p_z, 1024, nullptr, 0, 0, hout);
        hin = hout;
    }

    k_hmma<ACT_RELU,2,false><<<gHv, 256, SMEM_BYTES>>>(
        hin, 512, p_wor, 512, p_inp, p_wor + H_*H_,
        bo, nullptr, nullptr, 0, nullptr, 0, 0, p_out);

    k_hmma<ACT_NONE,1,true><<<gFin, 256, SMEM_BYTES>>>(
        p_out, K2_, p_wc, K2_, nullptr, nullptr,
        nullptr, nullptr, nullptr, 0, p_part, C_, C_, nullptr);
    k_reduce<<<(R_*C_ + 255)/256, 256>>>(bc, out);
}